// round 16
// baseline (speedup 1.0000x reference)
#include <cuda_runtime.h>
#include <cuda_bf16.h>
#include <math.h>
#include <stdint.h>

// DelayAndSum: out[b,t] = (1/128) * sum_s x[b, t+d_s, s], zero past T.
// d_s = rint(s*sin(0.5235987755982988)/2) in [0,32].
//
// R16: block-parallel decomposition. Ring accumulator reset per 32-row
// block h gives Y[h] (block-h rows -> output block h) and X[h] (-> output
// block h-1); out[h] = Y[h] + X[h+1]. Blocks assigned round-robin across
// the CTA's 8 warps over a contiguous ~2.8MB region: CTA's aggregate DRAM
// demand is one sequential stream (144 chip-wide vs R9's 1152), while each
// warp keeps R9's 3-stage x 8 KB cp.async.bulk pipeline. X exchanged via a
// 2-round SMEM ring + per-round __syncthreads. CTA-last block's warp closes
// via a guarded 32-row global halo (zero-pad at batch end).

#define NTHREADS  256
#define WPB       8
#define CPB       9                   // CTAs per batch -> 144 CTAs
#define BPB       3125                // 32-row blocks per batch (T/32)
#define CHROWS    16
#define CHBYTES   (CHROWS * 512)      // 8192
#define NSTAGE    3

#define SM_STAGES   0
#define SM_XRING    (WPB * NSTAGE * CHBYTES)          // 196608
#define SM_MBAR     (SM_XRING + 2 * WPB * 32 * 4)     // 198656
#define SM_TOTAL    (SM_MBAR + WPB * NSTAGE * 8)      // 198848

__device__ __forceinline__ void mbar_wait(uint32_t mbar, uint32_t phase) {
    asm volatile(
        "{\n\t"
        ".reg .pred P1;\n\t"
        "WAIT_LOOP_%=:\n\t"
        "mbarrier.try_wait.parity.acquire.cta.shared::cta.b64 P1, [%0], %1, 0x989680;\n\t"
        "@P1 bra.uni WAIT_DONE_%=;\n\t"
        "bra.uni WAIT_LOOP_%=;\n\t"
        "WAIT_DONE_%=:\n\t"
        "}"
        :: "r"(mbar), "r"(phase) : "memory");
}

__global__ __launch_bounds__(NTHREADS, 1)
void das13_kernel(const float* __restrict__ x, float* __restrict__ out,
                  int T, uint4 cmask)
{
    extern __shared__ char smem[];
    const uint32_t smem_u32 = (uint32_t)__cvta_generic_to_shared(smem);

    const int w  = threadIdx.x >> 5;
    const int m  = threadIdx.x & 31;
    const int c  = blockIdx.x;
    const int b  = c / CPB;
    const int cb = c % CPB;

    // CTA owns contiguous blocks [start, end) of its batch
    const int start = (cb * BPB) / CPB;
    const int end   = ((cb + 1) * BPB) / CPB;
    const int nblk  = end - start;                 // 347 or 348
    const int rounds = (nblk + WPB - 1) / WPB;     // 44

    // this warp's chunk count (2 chunks per owned block)
    const int nmyblk = (w < nblk) ? (nblk - w + WPB - 1) / WPB : 0;
    const int nch_my = nmyblk * 2;

    const float* __restrict__ xb = x + (size_t)b * (size_t)T * 128;
    float* __restrict__ outb = out + (size_t)b * T;
    float* xring = (float*)(smem + SM_XRING);      // [2][WPB][32]

    const uint32_t mbar0 = smem_u32 + SM_MBAR + w * (NSTAGE * 8);
    const uint32_t stg0  = smem_u32 + SM_STAGES + w * (NSTAGE * CHBYTES);

    // per-lane split mask: bit j set <=> d(4m+j) == m (row t+m), else d==m+1
    uint32_t mword = (m < 8)  ? cmask.x :
                     (m < 16) ? cmask.y :
                     (m < 24) ? cmask.z : cmask.w;
    uint32_t bits = (mword >> ((m & 7) * 4)) & 0xFu;
    const float f0 = (bits & 1u) ? 1.f : 0.f;
    const float f1 = (bits & 2u) ? 1.f : 0.f;
    const float f2 = (bits & 4u) ? 1.f : 0.f;
    const float f3 = (bits & 8u) ? 1.f : 0.f;
    const float inv = 1.0f / 128.0f;

    // chunk ordinal j (0..nch_my-1) -> global row of its 16-row span
    // block ordinal = j>>1 -> batch block = start + WPB*(j>>1) + w
    #define CHUNK_ROW(j) ((size_t)(32 * (start + WPB * ((j) >> 1) + w) \
                                   + 16 * ((j) & 1)))

    // init this warp's mbarriers
    if (m == 0) {
        #pragma unroll
        for (int s = 0; s < NSTAGE; ++s)
            asm volatile("mbarrier.init.shared.b64 [%0], %1;"
                         :: "r"(mbar0 + s * 8), "r"(1) : "memory");
    }
    __syncwarp();

    // prologue: fill the 3-stage pipeline
    if (m == 0) {
        #pragma unroll
        for (int j = 0; j < NSTAGE; ++j) {
            if (j < nch_my) {
                uint32_t bar = mbar0 + j * 8;
                uint32_t dst = stg0 + j * CHBYTES;
                const void* src = (const void*)(xb + CHUNK_ROW(j) * 128);
                asm volatile("mbarrier.arrive.expect_tx.shared.b64 _, [%0], %1;"
                             :: "r"(bar), "r"(CHBYTES) : "memory");
                asm volatile(
                    "cp.async.bulk.shared::cluster.global.mbarrier::complete_tx::bytes "
                    "[%0], [%1], %2, [%3];"
                    :: "r"(dst), "l"(src), "r"(CHBYTES), "r"(bar) : "memory");
            }
        }
    }

    float Yprev = 0.f;
    int prev_write = 0;        // warp7: deferred write pending from prev round

    #pragma unroll 1
    for (int i = 0; i < rounds; ++i) {
        const int bi = WPB * i + w;                // block ordinal in CTA
        const bool valid = bi < nblk;
        const bool is_last = (bi == nblk - 1);
        float Y = 0.f;

        if (valid) {
            float acc = 0.f, fin = 0.f;
            #pragma unroll
            for (int sub = 0; sub < 2; ++sub) {
                const int j = 2 * i + sub;
                const int s  = j % NSTAGE;
                const uint32_t ph = (uint32_t)((j / NSTAGE) & 1);
                mbar_wait(mbar0 + s * 8, ph);

                const float4* sb = (const float4*)(smem + w * (NSTAGE * CHBYTES)
                                                        + s * CHBYTES) + m;
                const int kbase = sub << 4;
                #pragma unroll
                for (int ii = 0; ii < CHROWS; ++ii) {
                    float4 v = sb[ii * 32];
                    float tot = (v.x + v.y) + (v.z + v.w);
                    float a = fmaf(v.x, f0, fmaf(v.y, f1, fmaf(v.z, f2, v.w * f3)));
                    float cc = tot - a;
                    int k = kbase + ii;
                    int r = (k - m) & 31;
                    float u1 = __shfl_sync(0xffffffffu, a, r);
                    float u2 = __shfl_sync(0xffffffffu, cc, (r + 31) & 31);
                    bool wrap = (r == 0);
                    float closed = acc + u2;
                    fin = wrap ? closed : fin;
                    acc = wrap ? u1 : acc + (u1 + u2);
                }
                __syncwarp();

                // refill this stage with chunk j+NSTAGE
                if (2 * i + sub + NSTAGE < nch_my && m == 0) {
                    const int jn = 2 * i + sub + NSTAGE;
                    asm volatile("fence.proxy.async.shared::cta;" ::: "memory");
                    uint32_t bar = mbar0 + s * 8;
                    uint32_t dst = stg0 + s * CHBYTES;
                    const void* src = (const void*)(xb + CHUNK_ROW(jn) * 128);
                    asm volatile("mbarrier.arrive.expect_tx.shared.b64 _, [%0], %1;"
                                 :: "r"(bar), "r"(CHBYTES) : "memory");
                    asm volatile(
                        "cp.async.bulk.shared::cluster.global.mbarrier::complete_tx::bytes "
                        "[%0], [%1], %2, [%3];"
                        :: "r"(dst), "l"(src), "r"(CHBYTES), "r"(bar) : "memory");
                }
            }
            Y = acc;
            xring[(i & 1) * (WPB * 32) + w * 32 + m] = fin;   // X[block bi]

            if (is_last) {
                // CTA-last block: successor X via guarded global halo rows
                const float* xbl = xb + 4 * m;
                float hacc = 0.f, hfin = 0.f;
                #pragma unroll 8
                for (int k = 0; k < 32; ++k) {
                    const int t = 32 * end + k;
                    float4 v = make_float4(0.f, 0.f, 0.f, 0.f);
                    if (t < T) v = *(const float4*)(xbl + (size_t)t * 128);
                    float tot = (v.x + v.y) + (v.z + v.w);
                    float a = fmaf(v.x, f0, fmaf(v.y, f1, fmaf(v.z, f2, v.w * f3)));
                    float cc = tot - a;
                    int r = (k - m) & 31;
                    float u1 = __shfl_sync(0xffffffffu, a, r);
                    float u2 = __shfl_sync(0xffffffffu, cc, (r + 31) & 31);
                    bool wrap = (r == 0);
                    float closed = hacc + u2;
                    hfin = wrap ? closed : hfin;
                    hacc = wrap ? u1 : hacc + (u1 + u2);
                }
                outb[32 * (end - 1) + m] = (Y + hfin) * inv;
            }
        }

        __syncthreads();

        // same-round closure for warps 0..6
        if (valid && !is_last && w < WPB - 1) {
            float xn = xring[(i & 1) * (WPB * 32) + (w + 1) * 32 + m];
            outb[32 * (start + bi) + m] = (Y + xn) * inv;
        }
        // warp7: deferred closure from previous round via warp0's X this round
        if (w == WPB - 1) {
            if (prev_write) {
                float xn = xring[(i & 1) * (WPB * 32) + 0 * 32 + m];
                outb[32 * (start + WPB * (i - 1) + WPB - 1) + m]
                    = (Yprev + xn) * inv;
            }
            Yprev = Y;
            prev_write = (valid && !is_last) ? 1 : 0;
        }
    }
    #undef CHUNK_ROW
}

extern "C" void kernel_launch(void* const* d_in, const int* in_sizes, int n_in,
                              void* d_out, int out_size)
{
    const float* x = (const float*)d_in[0];
    float* out = (float*)d_out;

    const int T = 100000;
    const int B = out_size / T;                    // 16

    // Host-side delay split mask (same libm as numpy's round path).
    double q = sin(0.5235987755982988);
    uint32_t cm[4] = {0u, 0u, 0u, 0u};
    for (int l = 0; l < 32; ++l) {
        uint32_t nib = 0u;
        for (int j = 0; j < 4; ++j) {
            int s = 4 * l + j;
            int d = (int)rint((double)s * q / 2.0);
            if (d == l) nib |= (1u << j);
        }
        cm[l >> 3] |= nib << ((l & 7) * 4);
    }
    uint4 cmask = make_uint4(cm[0], cm[1], cm[2], cm[3]);

    static int smem_set = 0;
    if (!smem_set) {
        cudaFuncSetAttribute(das13_kernel,
                             cudaFuncAttributeMaxDynamicSharedMemorySize,
                             SM_TOTAL);
        smem_set = 1;
    }

    const int grid = B * CPB;                      // 144 CTAs
    das13_kernel<<<grid, NTHREADS, SM_TOTAL>>>(x, out, T, cmask);
}

// round 17
// speedup vs baseline: 1.0188x; 1.0188x over previous
#include <cuda_runtime.h>
#include <cuda_bf16.h>
#include <math.h>
#include <stdint.h>

// DelayAndSum: out[b,t] = (1/128) * sum_s x[b, t+d_s, s], zero past T.
// d_s = rint(s*sin(0.5235987755982988)/2) in [0,32].
//
// FINAL (= R9 champion, 127.5 us, 83.6% DRAM): bulk-copy streaming.
// Each warp owns a contiguous run of 32-row blocks within one batch.
// Global reads happen ONLY via cp.async.bulk (UBLKCP): 8 KB (16-row)
// contiguous chunks into a private 3-stage SMEM ring, mbarrier completion,
// ~24 KB in flight per warp. Compute = ring accumulator (one LDS.128 +
// 2 shfl per row; lane m owns output == m mod 32). Warp boundaries close
// via SMEM partial exchange; CTA-edge warp does a guarded global halo.
// 8 warps/CTA, 192 KB stages -> 1 CTA/SM, 144 CTAs (9 per batch).
//
// Post-sweep verdict (R10-R16): chunk size, warp count, CTA count, L2
// policy, L2 prefetch, load balance, and stream consolidation all regress
// or are neutral; ~6.6 TB/s is the practical HBM ceiling for this pattern
// and traffic is within 1% of the 826 MB floor.

#define NTHREADS  256
#define WPB       8
#define CPB       9                   // CTAs per batch
#define WPBATCH   (WPB * CPB)         // 72
#define BPB       3125                // 32-row blocks per batch (T/32)
#define BASE_BLK  (BPB / WPBATCH)     // 43
#define EXTRA     (BPB % WPBATCH)     // 29
#define CHROWS    16
#define CHBYTES   (CHROWS * 512)      // 8192
#define NSTAGE    3

#define SM_STAGES   0
#define SM_SOPEN    (WPB * NSTAGE * CHBYTES)          // 196608
#define SM_MBAR     (SM_SOPEN + WPB * 32 * 4)         // 197632
#define SM_TOTAL    (SM_MBAR + WPB * NSTAGE * 8)      // 197824

__device__ __forceinline__ void mbar_wait(uint32_t mbar, uint32_t phase) {
    asm volatile(
        "{\n\t"
        ".reg .pred P1;\n\t"
        "WAIT_LOOP_%=:\n\t"
        "mbarrier.try_wait.parity.acquire.cta.shared::cta.b64 P1, [%0], %1, 0x989680;\n\t"
        "@P1 bra.uni WAIT_DONE_%=;\n\t"
        "bra.uni WAIT_LOOP_%=;\n\t"
        "WAIT_DONE_%=:\n\t"
        "}"
        :: "r"(mbar), "r"(phase) : "memory");
}

__global__ __launch_bounds__(NTHREADS, 1)
void das6_kernel(const float* __restrict__ x, float* __restrict__ out,
                 int T, uint4 cmask)
{
    extern __shared__ char smem[];
    const uint32_t smem_u32 =
        (uint32_t)__cvta_generic_to_shared(smem);

    const int w  = threadIdx.x >> 5;
    const int m  = threadIdx.x & 31;
    const int c  = blockIdx.x;
    const int b  = c / CPB;
    const int cb = c % CPB;
    const int wb = cb * WPB + w;

    const int start_blk = wb * BASE_BLK + (wb < EXTRA ? wb : EXTRA);
    const int nblk      = BASE_BLK + (wb < EXTRA ? 1 : 0);
    const int t0  = start_blk * 32;
    const int t1  = t0 + nblk * 32;
    const int nch = nblk * 2;                     // 16-row chunks

    const float* __restrict__ xb = x + (size_t)b * (size_t)T * 128;
    float* __restrict__ outb = out + (size_t)b * T;
    float* sopen = (float*)(smem + SM_SOPEN);

    const uint32_t mbar0 = smem_u32 + SM_MBAR + w * (NSTAGE * 8);
    const uint32_t stg0  = smem_u32 + SM_STAGES + w * (NSTAGE * CHBYTES);

    // per-lane split mask: bit j set <=> d(4m+j) == m (row t+m), else d==m+1
    uint32_t mword = (m < 8)  ? cmask.x :
                     (m < 16) ? cmask.y :
                     (m < 24) ? cmask.z : cmask.w;
    uint32_t bits = (mword >> ((m & 7) * 4)) & 0xFu;
    const float f0 = (bits & 1u) ? 1.f : 0.f;
    const float f1 = (bits & 2u) ? 1.f : 0.f;
    const float f2 = (bits & 4u) ? 1.f : 0.f;
    const float f3 = (bits & 8u) ? 1.f : 0.f;
    const float inv = 1.0f / 128.0f;

    // init this warp's mbarriers
    if (m == 0) {
        #pragma unroll
        for (int s = 0; s < NSTAGE; ++s)
            asm volatile("mbarrier.init.shared.b64 [%0], %1;"
                         :: "r"(mbar0 + s * 8), "r"(1) : "memory");
    }
    __syncwarp();

    // prologue: fill the 3-stage pipeline
    if (m == 0) {
        #pragma unroll
        for (int h = 0; h < NSTAGE; ++h) {
            uint32_t bar = mbar0 + h * 8;
            uint32_t dst = stg0 + h * CHBYTES;
            const void* src = (const void*)(xb + (size_t)(t0 + h * CHROWS) * 128);
            asm volatile("mbarrier.arrive.expect_tx.shared.b64 _, [%0], %1;"
                         :: "r"(bar), "r"(CHBYTES) : "memory");
            asm volatile(
                "cp.async.bulk.shared::cluster.global.mbarrier::complete_tx::bytes "
                "[%0], [%1], %2, [%3];"
                :: "r"(dst), "l"(src), "r"(CHBYTES), "r"(bar) : "memory");
        }
    }

    float acc = 0.f, fin = 0.f, open_fin = 0.f;

    #pragma unroll 1
    for (int h = 0; h < nch; ++h) {
        const int s  = h % NSTAGE;
        const uint32_t ph = (uint32_t)((h / NSTAGE) & 1);
        mbar_wait(mbar0 + s * 8, ph);

        const float4* sb = (const float4*)(smem + w * (NSTAGE * CHBYTES)
                                                + s * CHBYTES) + m;
        const int kbase = (h & 1) << 4;
        #pragma unroll
        for (int i = 0; i < CHROWS; ++i) {
            float4 v = sb[i * 32];
            float tot = (v.x + v.y) + (v.z + v.w);
            float a = fmaf(v.x, f0, fmaf(v.y, f1, fmaf(v.z, f2, v.w * f3)));
            float cc = tot - a;
            int k = kbase + i;
            int r = (k - m) & 31;
            float u1 = __shfl_sync(0xffffffffu, a, r);
            float u2 = __shfl_sync(0xffffffffu, cc, (r + 31) & 31);
            bool wrap = (r == 0);
            float closed = acc + u2;
            fin = wrap ? closed : fin;
            acc = wrap ? u1 : acc + (u1 + u2);
        }
        __syncwarp();

        // reuse this stage for chunk h+3
        if (h + NSTAGE < nch && m == 0) {
            asm volatile("fence.proxy.async.shared::cta;" ::: "memory");
            uint32_t bar = mbar0 + s * 8;
            uint32_t dst = stg0 + s * CHBYTES;
            const void* src =
                (const void*)(xb + (size_t)(t0 + (h + NSTAGE) * CHROWS) * 128);
            asm volatile("mbarrier.arrive.expect_tx.shared.b64 _, [%0], %1;"
                         :: "r"(bar), "r"(CHBYTES) : "memory");
            asm volatile(
                "cp.async.bulk.shared::cluster.global.mbarrier::complete_tx::bytes "
                "[%0], [%1], %2, [%3];"
                :: "r"(dst), "l"(src), "r"(CHBYTES), "r"(bar) : "memory");
        }

        if (h & 1) {
            const int lb = h >> 1;
            if (lb == 0)
                open_fin = fin;      // partials for outputs [t0-32, t0)
            else
                outb[t0 + lb * 32 - 32 + m] = fin * inv;
        }
    }
    // acc holds partials for outputs [t1-32, t1) (lane m -> t1-32+m)

    sopen[w * 32 + m] = open_fin;

    if (w == WPB - 1) {
        // CTA-edge warp: close boundary via guarded global halo rows
        const float* xbl = xb + 4 * m;
        #pragma unroll 8
        for (int k = 0; k < 32; ++k) {
            const int t = t1 + k;
            float4 v = make_float4(0.f, 0.f, 0.f, 0.f);
            if (t < T) v = *(const float4*)(xbl + (size_t)t * 128);
            float tot = (v.x + v.y) + (v.z + v.w);
            float a = fmaf(v.x, f0, fmaf(v.y, f1, fmaf(v.z, f2, v.w * f3)));
            float cc = tot - a;
            int r = (k - m) & 31;
            float u1 = __shfl_sync(0xffffffffu, a, r);
            float u2 = __shfl_sync(0xffffffffu, cc, (r + 31) & 31);
            bool wrap = (r == 0);
            float closed = acc + u2;
            fin = wrap ? closed : fin;
            acc = wrap ? u1 : acc + (u1 + u2);
        }
        outb[t1 - 32 + m] = fin * inv;
    }

    __syncthreads();

    if (w < WPB - 1) {
        float final = acc + sopen[(w + 1) * 32 + m];
        outb[t1 - 32 + m] = final * inv;
    }
}

extern "C" void kernel_launch(void* const* d_in, const int* in_sizes, int n_in,
                              void* d_out, int out_size)
{
    const float* x = (const float*)d_in[0];
    float* out = (float*)d_out;

    const int T = 100000;
    const int B = out_size / T;                    // 16

    // Host-side delay split mask (same libm as numpy's round path).
    double q = sin(0.5235987755982988);
    uint32_t cm[4] = {0u, 0u, 0u, 0u};
    for (int l = 0; l < 32; ++l) {
        uint32_t nib = 0u;
        for (int j = 0; j < 4; ++j) {
            int s = 4 * l + j;
            int d = (int)rint((double)s * q / 2.0);
            if (d == l) nib |= (1u << j);
        }
        cm[l >> 3] |= nib << ((l & 7) * 4);
    }
    uint4 cmask = make_uint4(cm[0], cm[1], cm[2], cm[3]);

    static int smem_set = 0;
    if (!smem_set) {
        cudaFuncSetAttribute(das6_kernel,
                             cudaFuncAttributeMaxDynamicSharedMemorySize,
                             SM_TOTAL);
        smem_set = 1;
    }

    const int grid = B * CPB;                      // 144 CTAs
    das6_kernel<<<grid, NTHREADS, SM_TOTAL>>>(x, out, T, cmask);
}